// round 16
// baseline (speedup 1.0000x reference)
#include <cuda_runtime.h>
#include <cuda_bf16.h>
#include <cstdint>

#define B_  512
#define T_  64
#define H_  512
#define G_  1536
#define KP0 320

// ---------------- scratch ----------------------------------------------------
__device__ float g_gx0 [(size_t)B_ * T_ * 2 * G_];
__device__ float g_gx1 [(size_t)B_ * T_ * G_];
__device__ float g_gx1b[(size_t)B_ * G_];
__device__ float g_hfin[(size_t)B_ * H_];
__device__ float g_lastb[(size_t)B_ * H_];
__device__ unsigned g_bar[2048];
__device__ __align__(16) __nv_bfloat16 g_hhi [2 * 2 * B_ * H_];
__device__ __align__(16) __nv_bfloat16 g_hlo [2 * 2 * B_ * H_];
__device__ __align__(16) __nv_bfloat16 g_a0hi[(size_t)B_ * T_ * KP0];
__device__ __align__(16) __nv_bfloat16 g_a0lo[(size_t)B_ * T_ * KP0];
__device__ __align__(16) __nv_bfloat16 g_w0hi[(size_t)2 * G_ * KP0];
__device__ __align__(16) __nv_bfloat16 g_w0lo[(size_t)2 * G_ * KP0];
__device__ __align__(16) __nv_bfloat16 g_a1hi[(size_t)B_ * T_ * 2 * H_];
__device__ __align__(16) __nv_bfloat16 g_a1lo[(size_t)B_ * T_ * 2 * H_];
__device__ __align__(16) __nv_bfloat16 g_w1hi[(size_t)2 * G_ * 2 * H_];
__device__ __align__(16) __nv_bfloat16 g_w1lo[(size_t)2 * G_ * 2 * H_];
__device__ __align__(16) __nv_bfloat16 g_wh0hi[(size_t)2 * G_ * H_];
__device__ __align__(16) __nv_bfloat16 g_wh0lo[(size_t)2 * G_ * H_];
__device__ __align__(16) __nv_bfloat16 g_wh1hi[(size_t)2 * G_ * H_];
__device__ __align__(16) __nv_bfloat16 g_wh1lo[(size_t)2 * G_ * H_];

// ---------------- helpers ----------------------------------------------------
__device__ __forceinline__ uint32_t smem_u32(const void* p) {
    uint32_t a;
    asm("{ .reg .u64 t; cvta.to.shared.u64 t, %1; cvt.u32.u64 %0, t; }" : "=r"(a) : "l"(p));
    return a;
}
#define CP16(sm, gp)  asm volatile("cp.async.cg.shared.global [%0], [%1], 16;" :: "r"(sm), "l"(gp))
#define CP_COMMIT()   asm volatile("cp.async.commit_group;" ::: "memory")
#define CP_WAIT(n)    asm volatile("cp.async.wait_group %0;" :: "n"(n) : "memory")

__device__ __forceinline__ void ldsm4(uint32_t* r, uint32_t a) {
    asm volatile("ldmatrix.sync.aligned.m8n8.x4.shared.b16 {%0,%1,%2,%3}, [%4];"
        : "=r"(r[0]), "=r"(r[1]), "=r"(r[2]), "=r"(r[3]) : "r"(a));
}
__device__ __forceinline__ void ldsm2(uint32_t* r, uint32_t a) {
    asm volatile("ldmatrix.sync.aligned.m8n8.x2.shared.b16 {%0,%1}, [%2];"
        : "=r"(r[0]), "=r"(r[1]) : "r"(a));
}
__device__ __forceinline__ void mma16816(float* c, const uint32_t* a, const uint32_t* b) {
    asm volatile("mma.sync.aligned.m16n8k16.row.col.f32.bf16.bf16.f32 "
        "{%0,%1,%2,%3},{%4,%5,%6,%7},{%8,%9},{%0,%1,%2,%3};"
        : "+f"(c[0]), "+f"(c[1]), "+f"(c[2]), "+f"(c[3])
        : "r"(a[0]), "r"(a[1]), "r"(a[2]), "r"(a[3]), "r"(b[0]), "r"(b[1]));
}
__device__ __forceinline__ float sigm(float x) { return __fdividef(1.f, 1.f + __expf(-x)); }
__device__ __forceinline__ float tanh_(float x) { return 2.f * sigm(2.f * x) - 1.f; }

// ---------------- prep kernels ----------------------------------------------
__global__ void embed_split_kernel(const int* __restrict__ tokens,
                                   const float* __restrict__ emb,
                                   __nv_bfloat16* __restrict__ hi,
                                   __nv_bfloat16* __restrict__ lo)
{
    const int blk = blockIdx.x;
    const int t = blk / B_;
    const int b = blk - t * B_;
    const int tok = tokens[b * T_ + t];
    const float* src = emb + (size_t)tok * 300;
    size_t dst = (size_t)blk * KP0;
    for (int e = threadIdx.x; e < KP0; e += blockDim.x) {
        float v = (e < 300) ? src[e] : 0.f;
        __nv_bfloat16 h = __float2bfloat16(v);
        hi[dst + e] = h;
        lo[dst + e] = __float2bfloat16(v - __bfloat162float(h));
    }
}

__global__ void split_pad_kernel(const float* __restrict__ src,
                                 __nv_bfloat16* __restrict__ hi,
                                 __nv_bfloat16* __restrict__ lo,
                                 int rows, int K, int Kp)
{
    size_t idx = (size_t)blockIdx.x * blockDim.x + threadIdx.x;
    if (idx >= (size_t)rows * Kp) return;
    int r = (int)(idx / Kp);
    int c = (int)(idx - (size_t)r * Kp);
    float v = (c < K) ? src[(size_t)r * K + c] : 0.f;
    __nv_bfloat16 h = __float2bfloat16(v);
    hi[idx] = h;
    lo[idx] = __float2bfloat16(v - __bfloat162float(h));
}

__global__ void zero_ctr_kernel(unsigned* __restrict__ p, int n)
{
    int i = blockIdx.x * blockDim.x + threadIdx.x;
    if (i < n) p[i] = 0u;
}

// ---------------- bf16-split GEMM, K-chunk 64, 3-stage single-sync ----------
#define GSTR 144
#define GTILE (128 * GSTR)
#define GSTAGE (4 * GTILE)
__global__ void __launch_bounds__(256, 1)
gemm_mma_split(const __nv_bfloat16* __restrict__ Ahi,
               const __nv_bfloat16* __restrict__ Alo,
               const __nv_bfloat16* __restrict__ Whi,
               const __nv_bfloat16* __restrict__ Wlo,
               const float* __restrict__ bias,
               float* __restrict__ C, int N, int Kp)
{
    extern __shared__ __align__(16) char smem[];
    const int tid = threadIdx.x;
    const int lane = tid & 31;
    const int wid = tid >> 5;
    const int wm = wid & 1, wn = wid >> 1;
    const int m0c = blockIdx.y * 128, n0c = blockIdx.x * 128;
    const int nchunks = Kp >> 6;
    const uint32_t sbase = smem_u32(smem);
    const __nv_bfloat16* bases[4] = { Ahi, Alo, Whi, Wlo };

    auto load_chunk = [&](int c, int s) {
        const uint32_t st = sbase + s * GSTAGE;
        #pragma unroll
        for (int q = 0; q < 16; q++) {
            int g = tid + q * 256;
            int tile = g >> 10, p = g & 1023;
            int r = p >> 3, seg = p & 7;
            int rowbase = (tile < 2) ? m0c : n0c;
            CP16(st + tile * GTILE + r * GSTR + seg * 16,
                 bases[tile] + (size_t)(rowbase + r) * Kp + c * 64 + seg * 8);
        }
        CP_COMMIT();
    };

    float acc[16][4];
    #pragma unroll
    for (int i = 0; i < 16; i++)
        #pragma unroll
        for (int j = 0; j < 4; j++) acc[i][j] = 0.f;

    load_chunk(0, 0);
    load_chunk(1, 1);
    for (int c = 0; c < nchunks; c++) {
        if (c + 1 < nchunks) { CP_WAIT(1); } else { CP_WAIT(0); }
        __syncthreads();
        if (c + 2 < nchunks) load_chunk(c + 2, (c + 2) % 3);
        const uint32_t st = sbase + (c % 3) * GSTAGE;
        #pragma unroll
        for (int kk = 0; kk < 4; kk++) {
            uint32_t ahi[4][4], alo[4][4], bhi[4][2], blo[4][2];
            #pragma unroll
            for (int i = 0; i < 4; i++) {
                int row = wm * 64 + i * 16 + (lane & 15);
                uint32_t off = row * GSTR + kk * 32 + (lane >> 4) * 16;
                ldsm4(ahi[i], st + off);
                ldsm4(alo[i], st + GTILE + off);
            }
            #pragma unroll
            for (int j = 0; j < 4; j++) {
                int row = wn * 32 + j * 8 + (lane & 7);
                uint32_t off = row * GSTR + kk * 32 + ((lane >> 3) & 1) * 16;
                ldsm2(bhi[j], st + 2 * GTILE + off);
                ldsm2(blo[j], st + 3 * GTILE + off);
            }
            #pragma unroll
            for (int i = 0; i < 4; i++)
                #pragma unroll
                for (int j = 0; j < 4; j++) {
                    mma16816(acc[i * 4 + j], ahi[i], bhi[j]);
                    mma16816(acc[i * 4 + j], ahi[i], blo[j]);
                    mma16816(acc[i * 4 + j], alo[i], bhi[j]);
                }
        }
    }
    __syncthreads();
    #pragma unroll
    for (int i = 0; i < 4; i++) {
        int m = m0c + wm * 64 + i * 16 + (lane >> 2);
        #pragma unroll
        for (int j = 0; j < 4; j++) {
            int n = n0c + wn * 32 + j * 8 + (lane & 3) * 2;
            float b0 = bias[n], b1 = bias[n + 1];
            float* a = acc[i * 4 + j];
            float2 v0 = { a[0] + b0, a[1] + b1 };
            float2 v1 = { a[2] + b0, a[3] + b1 };
            *reinterpret_cast<float2*>(C + (size_t)m * N + n) = v0;
            *reinterpret_cast<float2*>(C + (size_t)(m + 8) * N + n) = v1;
        }
    }
}

// ---------------- L0 scan: fully-streamed, 2 CTAs/SM, persistent ------------
// grid (8,16,2) = 256 CTAs, MROWS=64. All 4 tiles cp.async per K-chunk(64).
// Stage = 2*64*144 + 2*96*144 = 46080 B; 2 stages = 92160 -> 2 CTAs/SM.
#define ASTR 144
#define SA_PL (64 * ASTR)
#define SW_PL (96 * ASTR)
#define SSTG (2 * SA_PL + 2 * SW_PL)
__global__ void __launch_bounds__(256, 2)
gru_scan_stream(__nv_bfloat16* __restrict__ hhi_A, __nv_bfloat16* __restrict__ hlo_A,
                __nv_bfloat16* __restrict__ hhi_B, __nv_bfloat16* __restrict__ hlo_B,
                const float* __restrict__ gx, int gx_ld, int gx_ds,
                const __nv_bfloat16* __restrict__ whh_hi,
                const __nv_bfloat16* __restrict__ whh_lo,
                const float* __restrict__ bhh,
                __nv_bfloat16* __restrict__ y_hi, __nv_bfloat16* __restrict__ y_lo,
                unsigned* __restrict__ bars)
{
    constexpr int NCH = 8;
    constexpr int NE = 8;                   // MFRG=2 * 4

    extern __shared__ __align__(16) char smem[];
    const int tid = threadIdx.x;
    const int lane = tid & 31;
    const int wid = tid >> 5;
    const int wm = wid & 1, wn = wid >> 1;
    const int d  = blockIdx.z;
    const int b0 = blockIdx.x * 64;
    const int j0 = blockIdx.y * 32;
    const uint32_t sb = smem_u32(smem);
    unsigned* ctr = bars + (blockIdx.x * gridDim.z + blockIdx.z) * 32;
    const unsigned members = gridDim.y;

    const __nv_bfloat16* Wh = whh_hi + (size_t)d * G_ * H_;
    const __nv_bfloat16* Wl = whh_lo + (size_t)d * G_ * H_;
    const float* bhh_d = bhh + d * G_;

    int eb[NE], ej[NE];
    {
        int q = 0;
        #pragma unroll
        for (int i = 0; i < 2; i++)
            #pragma unroll
            for (int half = 0; half < 2; half++)
                #pragma unroll
                for (int e = 0; e < 2; e++) {
                    eb[q] = b0 + wm * 32 + i * 16 + (lane >> 2) + half * 8;
                    ej[q] = j0 + wn * 8 + (lane & 3) * 2 + e;
                    q++;
                }
    }

    float hprev[NE];
    #pragma unroll
    for (int q = 0; q < NE; q++) hprev[q] = 0.f;

    float gxp[NE][3];
    auto prefetch_gx = [&](int ss) {
        const int tt = (d == 0) ? ss : (T_ - 1 - ss);
        #pragma unroll
        for (int q = 0; q < NE; q++) {
            const float* gxr = gx + ((size_t)tt * B_ + eb[q]) * gx_ld + (size_t)d * gx_ds;
            gxp[q][0] = __ldcg(gxr + ej[q]);
            gxp[q][1] = __ldcg(gxr + H_ + ej[q]);
            gxp[q][2] = __ldcg(gxr + 2 * H_ + ej[q]);
        }
    };
    prefetch_gx(0);

    const __nv_bfloat16 *phh = hhi_A, *phl = hlo_A;
    __nv_bfloat16 *nhh = hhi_B, *nhl = hlo_B;

    for (int s = 0; s < T_; s++) {
        const int t = (d == 0) ? s : (T_ - 1 - s);

        float acc[3][2][4];
        #pragma unroll
        for (int g = 0; g < 3; g++)
            #pragma unroll
            for (int i = 0; i < 2; i++)
                #pragma unroll
                for (int r = 0; r < 4; r++) acc[g][i][r] = 0.f;

        if (s > 0) {
            const __nv_bfloat16* Ah = phh + (size_t)d * B_ * H_;
            const __nv_bfloat16* Al = phl + (size_t)d * B_ * H_;

            auto load_chunk = [&](int c, int st) {
                const uint32_t base = sb + st * SSTG;
                #pragma unroll
                for (int q = 0; q < 10; q++) {          // 2560 pieces
                    int g = tid + q * 256;
                    uint32_t soff;
                    const __nv_bfloat16* gp;
                    if (g < 1024) {
                        int plane = (g >= 512);
                        int p = g & 511;
                        int row = p >> 3, seg = p & 7;
                        gp = (plane ? Al : Ah) + (size_t)(b0 + row) * H_ + c * 64 + seg * 8;
                        soff = base + plane * SA_PL + row * ASTR + seg * 16;
                    } else {
                        int gw = g - 1024;
                        int plane = (gw >= 768);
                        int p = gw - plane * 768;
                        int row = p >> 3, seg = p & 7;
                        int grow = (row >> 5) * H_ + j0 + (row & 31);
                        gp = (plane ? Wl : Wh) + (size_t)grow * H_ + c * 64 + seg * 8;
                        soff = base + 2 * SA_PL + plane * SW_PL + row * ASTR + seg * 16;
                    }
                    CP16(soff, gp);
                }
                CP_COMMIT();
            };

            load_chunk(0, 0);
            for (int c = 0; c < NCH; c++) {
                const int st = c & 1;
                if (c + 1 < NCH) { load_chunk(c + 1, st ^ 1); CP_WAIT(1); }
                else             { CP_WAIT(0); }
                __syncthreads();
                const uint32_t base = sb + st * SSTG;
                #pragma unroll
                for (int kk = 0; kk < 4; kk++) {
                    uint32_t ah[2][4], al[2][4];
                    #pragma unroll
                    for (int i = 0; i < 2; i++) {
                        int row = wm * 32 + i * 16 + (lane & 15);
                        uint32_t off = row * ASTR + kk * 32 + (lane >> 4) * 16;
                        ldsm4(ah[i], base + off);
                        ldsm4(al[i], base + SA_PL + off);
                    }
                    uint32_t bh[3][2], bl[3][2];
                    #pragma unroll
                    for (int g = 0; g < 3; g++) {
                        int row = g * 32 + wn * 8 + (lane & 7);
                        uint32_t off = 2 * SA_PL + row * ASTR + kk * 32 + ((lane >> 3) & 1) * 16;
                        ldsm2(bh[g], base + off);
                        ldsm2(bl[g], base + SW_PL + off);
                    }
                    #pragma unroll
                    for (int g = 0; g < 3; g++)
                        #pragma unroll
                        for (int i = 0; i < 2; i++) {
                            mma16816(acc[g][i], ah[i], bh[g]);
                            mma16816(acc[g][i], ah[i], bl[g]);
                            mma16816(acc[g][i], al[i], bh[g]);
                        }
                }
                __syncthreads();
            }
        }

        // -------- register-local gate epilogue --------
        #pragma unroll
        for (int q = 0; q < NE; q++) {
            const int i = q >> 2;
            const int r2 = q & 3;
            const int j = ej[q];
            float ghr = acc[0][i][r2] + bhh_d[j];
            float ghz = acc[1][i][r2] + bhh_d[H_ + j];
            float ghn = acc[2][i][r2] + bhh_d[2 * H_ + j];
            float rg = sigm(gxp[q][0] + ghr);
            float zg = sigm(gxp[q][1] + ghz);
            float ng = tanh_(gxp[q][2] + rg * ghn);
            float hv = (1.f - zg) * ng + zg * hprev[q];
            hprev[q] = hv;
            size_t ho = ((size_t)d * B_ + eb[q]) * H_ + j;
            __nv_bfloat16 hib = __float2bfloat16(hv);
            __nv_bfloat16 lob = __float2bfloat16(hv - __bfloat162float(hib));
            nhh[ho] = hib;
            nhl[ho] = lob;
            size_t yo = ((size_t)t * B_ + eb[q]) * (size_t)(2 * H_) + (size_t)d * H_ + j;
            y_hi[yo] = hib;
            y_lo[yo] = lob;
        }

        if (s + 1 < T_) {
            __syncthreads();
            if (tid == 0) { __threadfence(); atomicAdd(ctr, 1u); }
            prefetch_gx(s + 1);
            if (tid == 0) {
                volatile unsigned* vc = ctr;
                while (*vc < (unsigned)(s + 1) * members) { }
                __threadfence();
            }
            __syncthreads();
        }

        const __nv_bfloat16* th = phh; phh = nhh; nhh = (__nv_bfloat16*)th;
        const __nv_bfloat16* tl = phl; phl = nhl; nhl = (__nv_bfloat16*)tl;
    }
}

// ---------------- L1 scan: W-hi resident (round-15 proven) ------------------
#define WHI_B (96 * 1024)
template<int MROWS>
__global__ void __launch_bounds__(256, 1)
gru_scan_wres(__nv_bfloat16* __restrict__ hhi_A, __nv_bfloat16* __restrict__ hlo_A,
              __nv_bfloat16* __restrict__ hhi_B, __nv_bfloat16* __restrict__ hlo_B,
              const float* __restrict__ gx, int gx_ld, int gx_ds,
              const __nv_bfloat16* __restrict__ whh_hi,
              const __nv_bfloat16* __restrict__ whh_lo,
              const float* __restrict__ bhh,
              float* __restrict__ hfin,
              unsigned* __restrict__ bars)
{
    constexpr int A_PL = MROWS * ASTR;
    constexpr int WLO_PL = 96 * ASTR;
    constexpr int STG = 2 * A_PL + WLO_PL;
    constexpr int NCH = 8;
    constexpr int A4 = MROWS * 8;
    constexpr int MFRG = MROWS / 32;
    constexpr int NE = MFRG * 4;

    extern __shared__ __align__(16) char smem[];
    const int tid = threadIdx.x;
    const int lane = tid & 31;
    const int wid = tid >> 5;
    const int wm = wid & 1, wn = wid >> 1;
    const int d  = blockIdx.z;
    const int b0 = blockIdx.x * MROWS;
    const int j0 = blockIdx.y * 32;
    const uint32_t sb = smem_u32(smem);
    const uint32_t sst = sb + WHI_B;
    unsigned* ctr = bars + (blockIdx.x * gridDim.z + blockIdx.z) * 32;
    const unsigned members = gridDim.y;

    const __nv_bfloat16* Wl = whh_lo + (size_t)d * G_ * H_;

    auto load_Wlo = [&](int c, int st) {
        const uint32_t base = sst + st * STG + 2 * A_PL;
        #pragma unroll
        for (int q = 0; q < 3; q++) {
            int g = tid + q * 256;
            int row = g >> 3, seg = g & 7;
            int grow = (row >> 5) * H_ + j0 + (row & 31);
            CP16(base + row * ASTR + seg * 16, Wl + (size_t)grow * H_ + c * 64 + seg * 8);
        }
    };

    {
        const __nv_bfloat16* Wh = whh_hi + (size_t)d * G_ * H_;
        for (int g = tid; g < 96 * 64; g += 256) {
            int row = g >> 6, seg = g & 63;
            int grow = (row >> 5) * H_ + j0 + (row & 31);
            uint32_t off = (row << 10) + (((uint32_t)seg * 16) ^ ((row & 7) << 4));
            CP16(sb + off, Wh + (size_t)grow * H_ + seg * 8);
        }
        CP_COMMIT(); CP_WAIT(0);
        __syncthreads();
    }
    const float* bhh_d = bhh + d * G_;

    int eb[NE], ej[NE];
    {
        int q = 0;
        #pragma unroll
        for (int i = 0; i < MFRG; i++)
            #pragma unroll
            for (int half = 0; half < 2; half++)
                #pragma unroll
                for (int e = 0; e < 2; e++) {
                    eb[q] = b0 + wm * (MROWS / 2) + i * 16 + (lane >> 2) + half * 8;
                    ej[q] = j0 + wn * 8 + (lane & 3) * 2 + e;
                    q++;
                }
    }

    float hprev[NE];
    #pragma unroll
    for (int q = 0; q < NE; q++) hprev[q] = 0.f;

    float gxp[NE][3];
    auto prefetch_gx = [&](int ss) {
        const int tt = (d == 0) ? ss : (T_ - 1 - ss);
        #pragma unroll
        for (int q = 0; q < NE; q++) {
            const float* gxr = gx + ((size_t)tt * B_ + eb[q]) * gx_ld + (size_t)d * gx_ds;
            gxp[q][0] = __ldcg(gxr + ej[q]);
            gxp[q][1] = __ldcg(gxr + H_ + ej[q]);
            gxp[q][2] = __ldcg(gxr + 2 * H_ + ej[q]);
        }
    };
    prefetch_gx(0);

    const __nv_bfloat16 *phh = hhi_A, *phl = hlo_A;
    __nv_bfloat16 *nhh = hhi_B, *nhl = hlo_B;

    for (int s = 0; s < T_; s++) {
        float acc[3][MFRG][4];
        #pragma unroll
        for (int g = 0; g < 3; g++)
            #pragma unroll
            for (int i = 0; i < MFRG; i++)
                #pragma unroll
                for (int r = 0; r < 4; r++) acc[g][i][r] = 0.f;

        if (s > 0) {
            const __nv_bfloat16* Ah = phh + (size_t)d * B_ * H_;
            const __nv_bfloat16* Al = phl + (size_t)d * B_ * H_;

            auto load_A = [&](int c, int st) {
                const uint32_t base = sst + st * STG;
                #pragma unroll
                for (int q = 0; q < (2 * A4) / 256; q++) {
                    int g = tid + q * 256;
                    int plane = (g >= A4);
                    int p = plane ? g - A4 : g;
                    int row = p >> 3, seg = p & 7;
                    CP16(base + plane * A_PL + row * ASTR + seg * 16,
                         (plane ? Al : Ah) + (size_t)(b0 + row) * H_ + c * 64 + seg * 8);
                }
            };

            load_A(0, 0); CP_COMMIT();
            for (int c = 0; c < NCH; c++) {
                const int st = c & 1;
                if (c + 1 < NCH) {
                    load_A(c + 1, st ^ 1);
                    if (c + 1 >= 2) load_Wlo(c + 1, st ^ 1);
                    CP_COMMIT();
                    CP_WAIT(1);
                } else {
                    CP_WAIT(0);
                }
                __syncthreads();
                const uint32_t base = sst + st * STG;
                #pragma unroll
                for (int kk = 0; kk < 4; kk++) {
                    uint32_t ah[MFRG][4], al[MFRG][4];
                    #pragma unroll
                    for (int i = 0; i < MFRG; i++) {
                        int row = wm * (MROWS / 2) + i * 16 + (lane & 15);
                        uint32_t off = row * ASTR + kk * 32 + (lane >> 4) * 16;
                        ldsm4(ah[i], base + off);
                        ldsm4(al[i], base + A_PL + off);
                    }
                    uint32_t bh[3][2], bl[3][2];
                    #pragma unroll
                    for (int g = 0; g < 3; g++) {
                        int row = g * 32 + wn * 8 + (lane & 7);
                        uint32_t koff = (uint32_t)(c * 128 + kk * 32 + ((lane >> 3) & 1) * 16);
                        ldsm2(bh[g], sb + (row << 10) + (koff ^ ((row & 7) << 4)));
                        ldsm2(bl[g], base + 2 * A_PL + row * ASTR + kk * 32 + ((lane >> 3) & 1) * 16);
                    }
                    #pragma unroll
                    for (int g = 0; g < 3; g++)
                        #pragma unroll
                        for (int i = 0; i < MFRG; i++) {
                            mma16816(acc[g][i], ah[i], bh[g]);
                            mma16816(acc[g][i], ah[i], bl[g]);
                            mma16816(acc[g][i], al[i], bh[g]);
                        }
                }
                __syncthreads();
            }
        }

        #pragma unroll
        for (int q = 0; q < NE; q++) {
            const int i = q >> 2;
            const int r2 = q & 3;
            const int j = ej[q];
            float ghr = acc[0][i][r2] + bhh_d[j];
            float ghz = acc[1][i][r2] + bhh_d[H_ + j];
            float ghn = acc[2][i][r2] + bhh_d[2 * H_ + j];
            float rg = sigm(gxp[q][0] + ghr);
            float zg = sigm(gxp[q][1] + ghz);
            float ng = tanh_(gxp[q][2] + rg * ghn);
            float hv = (1.f - zg) * ng + zg * hprev[q];
            hprev[q] = hv;
            size_t ho = ((size_t)d * B_ + eb[q]) * H_ + j;
            __nv_bfloat16 hib = __float2bfloat16(hv);
            __nv_bfloat16 lob = __float2bfloat16(hv - __bfloat162float(hib));
            nhh[ho] = hib;
            nhl[ho] = lob;
            if (hfin && s == T_ - 1)
                hfin[(size_t)eb[q] * H_ + j] = hv;
        }

        if (s + 1 < T_) {
            __syncthreads();
            if (tid == 0) { __threadfence(); atomicAdd(ctr, 1u); }
            load_Wlo(0, 0);
            load_Wlo(1, 1);
            CP_COMMIT();
            prefetch_gx(s + 1);
            if (tid == 0) {
                volatile unsigned* vc = ctr;
                while (*vc < (unsigned)(s + 1) * members) { }
                __threadfence();
            }
            __syncthreads();
        }

        const __nv_bfloat16* th = phh; phh = nhh; nhh = (__nv_bfloat16*)th;
        const __nv_bfloat16* tl = phl; phl = nhl; nhl = (__nv_bfloat16*)tl;
    }
}

// ---------------- tail kernels ----------------------------------------------
__global__ void bwd1_gates(const float* __restrict__ gxb,
                           const float* __restrict__ bhh,
                           float* __restrict__ out)
{
    int idx = blockIdx.x * blockDim.x + threadIdx.x;
    if (idx >= B_ * H_) return;
    int b = idx >> 9, j = idx & 511;
    const float* r0 = gxb + (size_t)b * G_;
    float rg = sigm(r0[j] + bhh[j]);
    float zg = sigm(r0[H_ + j] + bhh[H_ + j]);
    float ng = tanh_(r0[2 * H_ + j] + rg * bhh[2 * H_ + j]);
    out[idx] = (1.f - zg) * ng;
}

__global__ void fc_kernel(const float* __restrict__ hf, const float* __restrict__ hb,
                          const float* __restrict__ fcw, const float* __restrict__ fcb,
                          float* __restrict__ out)
{
    int b = blockIdx.x, tid = threadIdx.x;
    float s0 = 0.f, s1 = 0.f;
    for (int j = tid; j < 1024; j += 256) {
        float v = (j < 512) ? hf[(size_t)b * 512 + j] : hb[(size_t)b * 512 + (j - 512)];
        s0 += v * fcw[j];
        s1 += v * fcw[1024 + j];
    }
    __shared__ float red0[256], red1[256];
    red0[tid] = s0; red1[tid] = s1;
    __syncthreads();
    for (int off = 128; off > 0; off >>= 1) {
        if (tid < off) { red0[tid] += red0[tid + off]; red1[tid] += red1[tid + off]; }
        __syncthreads();
    }
    if (tid == 0) {
        out[b * 2 + 0] = red0[0] + fcb[0];
        out[b * 2 + 1] = red1[0] + fcb[1];
    }
}

// ---------------- launch -----------------------------------------------------
extern "C" void kernel_launch(void* const* d_in, const int* in_sizes, int n_in,
                              void* d_out, int out_size)
{
    (void)in_sizes; (void)n_in; (void)out_size;
    const int*   tokens = (const int*)  d_in[0];
    const float* emb    = (const float*)d_in[1];
    const float* w_ih0  = (const float*)d_in[2];
    const float* w_hh0  = (const float*)d_in[3];
    const float* b_ih0  = (const float*)d_in[4];
    const float* b_hh0  = (const float*)d_in[5];
    const float* w_ih1  = (const float*)d_in[6];
    const float* w_hh1  = (const float*)d_in[7];
    const float* b_ih1  = (const float*)d_in[8];
    const float* b_hh1  = (const float*)d_in[9];
    const float* fc_w   = (const float*)d_in[10];
    const float* fc_b   = (const float*)d_in[11];
    float* out = (float*)d_out;

    float *pgx0, *pgx1, *pgx1b, *phfin, *plastb;
    unsigned* pbar;
    cudaGetSymbolAddress((void**)&pgx0,   g_gx0);
    cudaGetSymbolAddress((void**)&pgx1,   g_gx1);
    cudaGetSymbolAddress((void**)&pgx1b,  g_gx1b);
    cudaGetSymbolAddress((void**)&phfin,  g_hfin);
    cudaGetSymbolAddress((void**)&plastb, g_lastb);
    cudaGetSymbolAddress((void**)&pbar,   g_bar);
    __nv_bfloat16 *phhi, *phlo, *pa0hi, *pa0lo, *pw0hi, *pw0lo;
    __nv_bfloat16 *pa1hi, *pa1lo, *pw1hi, *pw1lo, *pwh0hi, *pwh0lo, *pwh1hi, *pwh1lo;
    cudaGetSymbolAddress((void**)&phhi,  g_hhi);
    cudaGetSymbolAddress((void**)&phlo,  g_hlo);
    cudaGetSymbolAddress((void**)&pa0hi, g_a0hi);
    cudaGetSymbolAddress((void**)&pa0lo, g_a0lo);
    cudaGetSymbolAddress((void**)&pw0hi, g_w0hi);
    cudaGetSymbolAddress((void**)&pw0lo, g_w0lo);
    cudaGetSymbolAddress((void**)&pa1hi, g_a1hi);
    cudaGetSymbolAddress((void**)&pa1lo, g_a1lo);
    cudaGetSymbolAddress((void**)&pw1hi, g_w1hi);
    cudaGetSymbolAddress((void**)&pw1lo, g_w1lo);
    cudaGetSymbolAddress((void**)&pwh0hi, g_wh0hi);
    cudaGetSymbolAddress((void**)&pwh0lo, g_wh0lo);
    cudaGetSymbolAddress((void**)&pwh1hi, g_wh1hi);
    cudaGetSymbolAddress((void**)&pwh1lo, g_wh1lo);

    const int GSM  = 3 * GSTAGE;                                  // 221184
    const int SCMS = 2 * SSTG;                                    // 92160
    const int SCM1 = WHI_B + 2 * (2 * 64 * ASTR + 96 * ASTR);     // 162816
    cudaFuncSetAttribute(gemm_mma_split, cudaFuncAttributeMaxDynamicSharedMemorySize, GSM);
    cudaFuncSetAttribute(gru_scan_stream, cudaFuncAttributeMaxDynamicSharedMemorySize, SCMS);
    cudaFuncSetAttribute(gru_scan_wres<64>, cudaFuncAttributeMaxDynamicSharedMemorySize, SCM1);

    const size_t HB = (size_t)2 * B_ * H_;
    const int MT = B_ * T_;

    // 1) prep
    split_pad_kernel<<<(2 * G_ * KP0 + 255) / 256, 256>>>(w_ih0, pw0hi, pw0lo, 2 * G_, 300, KP0);
    embed_split_kernel<<<MT, 128>>>(tokens, emb, pa0hi, pa0lo);
    zero_ctr_kernel<<<8, 256>>>(pbar, 2048);
    split_pad_kernel<<<(2 * G_ * H_ + 255) / 256, 256>>>(w_hh0, pwh0hi, pwh0lo, 2 * G_, H_, H_);
    // 2) layer0 input GEMM: gx0[32768][3072]
    gemm_mma_split<<<dim3(2 * G_ / 128, MT / 128), 256, GSM>>>(
        pa0hi, pa0lo, pw0hi, pw0lo, b_ih0, pgx0, 2 * G_, KP0);
    // 3) layer0 scan: streaming, 2 CTAs/SM (256 CTAs)
    gru_scan_stream<<<dim3(8, 16, 2), 256, SCMS>>>(
        phhi, phlo, phhi + HB, phlo + HB,
        pgx0, 2 * G_, G_, pwh0hi, pwh0lo, b_hh0, pa1hi, pa1lo, pbar);
    // 4) remaining splits
    split_pad_kernel<<<(int)(((size_t)2 * G_ * 1024 + 255) / 256), 256>>>(w_ih1, pw1hi, pw1lo, 2 * G_, 1024, 1024);
    split_pad_kernel<<<(2 * G_ * H_ + 255) / 256, 256>>>(w_hh1, pwh1hi, pwh1lo, 2 * G_, H_, H_);
    // 5) layer1 fwd input GEMM: gx1[32768][1536]
    gemm_mma_split<<<dim3(G_ / 128, MT / 128), 256, GSM>>>(
        pa1hi, pa1lo, pw1hi, pw1lo, b_ih1, pgx1, G_, 1024);
    // 6) layer1 forward scan (W-resident, 128 CTAs)
    gru_scan_wres<64><<<dim3(8, 16, 1), 256, SCM1>>>(
        phhi, phlo, phhi + HB, phlo + HB,
        pgx1, G_, 0, pwh1hi, pwh1lo, b_hh1, phfin, pbar + 1024);
    // 7) layer1 backward = ONE step at t=T-1 (h0=0)
    gemm_mma_split<<<dim3(G_ / 128, B_ / 128), 256, GSM>>>(
        pa1hi + (size_t)(T_ - 1) * B_ * 1024, pa1lo + (size_t)(T_ - 1) * B_ * 1024,
        pw1hi + (size_t)G_ * 1024, pw1lo + (size_t)G_ * 1024,
        b_ih1 + G_, pgx1b, G_, 1024);
    bwd1_gates<<<(B_ * H_ + 255) / 256, 256>>>(pgx1b, b_hh1 + G_, plastb);
    // 8) FC head
    fc_kernel<<<B_, 256>>>(phfin, plastb, fc_w, fc_b, out);
}

// round 17
// speedup vs baseline: 1.1391x; 1.1391x over previous
#include <cuda_runtime.h>
#include <cuda_bf16.h>
#include <cstdint>

#define B_  512
#define T_  64
#define H_  512
#define G_  1536
#define KP0 320

// ---------------- scratch ----------------------------------------------------
__device__ float g_gx0 [(size_t)B_ * T_ * 2 * G_];
__device__ float g_gx1 [(size_t)B_ * T_ * G_];
__device__ float g_gx1b[(size_t)B_ * G_];
__device__ float g_hfin[(size_t)B_ * H_];
__device__ float g_lastb[(size_t)B_ * H_];
__device__ unsigned g_bar[2048];
__device__ __align__(16) __nv_bfloat16 g_hhi [2 * 2 * B_ * H_];
__device__ __align__(16) __nv_bfloat16 g_hlo [2 * 2 * B_ * H_];
__device__ __align__(16) __nv_bfloat16 g_a0hi[(size_t)B_ * T_ * KP0];
__device__ __align__(16) __nv_bfloat16 g_a0lo[(size_t)B_ * T_ * KP0];
__device__ __align__(16) __nv_bfloat16 g_w0hi[(size_t)2 * G_ * KP0];
__device__ __align__(16) __nv_bfloat16 g_w0lo[(size_t)2 * G_ * KP0];
__device__ __align__(16) __nv_bfloat16 g_a1hi[(size_t)B_ * T_ * 2 * H_];
__device__ __align__(16) __nv_bfloat16 g_a1lo[(size_t)B_ * T_ * 2 * H_];
__device__ __align__(16) __nv_bfloat16 g_w1hi[(size_t)2 * G_ * 2 * H_];
__device__ __align__(16) __nv_bfloat16 g_w1lo[(size_t)2 * G_ * 2 * H_];
__device__ __align__(16) __nv_bfloat16 g_wh0hi[(size_t)2 * G_ * H_];
__device__ __align__(16) __nv_bfloat16 g_wh0lo[(size_t)2 * G_ * H_];
__device__ __align__(16) __nv_bfloat16 g_wh1hi[(size_t)2 * G_ * H_];
__device__ __align__(16) __nv_bfloat16 g_wh1lo[(size_t)2 * G_ * H_];

// ---------------- helpers ----------------------------------------------------
__device__ __forceinline__ uint32_t smem_u32(const void* p) {
    uint32_t a;
    asm("{ .reg .u64 t; cvta.to.shared.u64 t, %1; cvt.u32.u64 %0, t; }" : "=r"(a) : "l"(p));
    return a;
}
#define CP16(sm, gp)  asm volatile("cp.async.cg.shared.global [%0], [%1], 16;" :: "r"(sm), "l"(gp))
#define CP_COMMIT()   asm volatile("cp.async.commit_group;" ::: "memory")
#define CP_WAIT(n)    asm volatile("cp.async.wait_group %0;" :: "n"(n) : "memory")

__device__ __forceinline__ void ldsm4(uint32_t* r, uint32_t a) {
    asm volatile("ldmatrix.sync.aligned.m8n8.x4.shared.b16 {%0,%1,%2,%3}, [%4];"
        : "=r"(r[0]), "=r"(r[1]), "=r"(r[2]), "=r"(r[3]) : "r"(a));
}
__device__ __forceinline__ void ldsm2(uint32_t* r, uint32_t a) {
    asm volatile("ldmatrix.sync.aligned.m8n8.x2.shared.b16 {%0,%1}, [%2];"
        : "=r"(r[0]), "=r"(r[1]) : "r"(a));
}
__device__ __forceinline__ void mma16816(float* c, const uint32_t* a, const uint32_t* b) {
    asm volatile("mma.sync.aligned.m16n8k16.row.col.f32.bf16.bf16.f32 "
        "{%0,%1,%2,%3},{%4,%5,%6,%7},{%8,%9},{%0,%1,%2,%3};"
        : "+f"(c[0]), "+f"(c[1]), "+f"(c[2]), "+f"(c[3])
        : "r"(a[0]), "r"(a[1]), "r"(a[2]), "r"(a[3]), "r"(b[0]), "r"(b[1]));
}
__device__ __forceinline__ float sigm(float x) { return __fdividef(1.f, 1.f + __expf(-x)); }
__device__ __forceinline__ float tanh_(float x) { return 2.f * sigm(2.f * x) - 1.f; }

// ---------------- prep kernels ----------------------------------------------
__global__ void embed_split_kernel(const int* __restrict__ tokens,
                                   const float* __restrict__ emb,
                                   __nv_bfloat16* __restrict__ hi,
                                   __nv_bfloat16* __restrict__ lo)
{
    const int blk = blockIdx.x;
    const int t = blk / B_;
    const int b = blk - t * B_;
    const int tok = tokens[b * T_ + t];
    const float* src = emb + (size_t)tok * 300;
    size_t dst = (size_t)blk * KP0;
    for (int e = threadIdx.x; e < KP0; e += blockDim.x) {
        float v = (e < 300) ? src[e] : 0.f;
        __nv_bfloat16 h = __float2bfloat16(v);
        hi[dst + e] = h;
        lo[dst + e] = __float2bfloat16(v - __bfloat162float(h));
    }
}

__global__ void split_pad_kernel(const float* __restrict__ src,
                                 __nv_bfloat16* __restrict__ hi,
                                 __nv_bfloat16* __restrict__ lo,
                                 int rows, int K, int Kp)
{
    size_t idx = (size_t)blockIdx.x * blockDim.x + threadIdx.x;
    if (idx >= (size_t)rows * Kp) return;
    int r = (int)(idx / Kp);
    int c = (int)(idx - (size_t)r * Kp);
    float v = (c < K) ? src[(size_t)r * K + c] : 0.f;
    __nv_bfloat16 h = __float2bfloat16(v);
    hi[idx] = h;
    lo[idx] = __float2bfloat16(v - __bfloat162float(h));
}

__global__ void zero_ctr_kernel(unsigned* __restrict__ p, int n)
{
    int i = blockIdx.x * blockDim.x + threadIdx.x;
    if (i < n) p[i] = 0u;
}

// ---------------- bf16-split GEMM, K-chunk 64, 3-stage single-sync ----------
#define GSTR 144
#define GTILE (128 * GSTR)
#define GSTAGE (4 * GTILE)
__global__ void __launch_bounds__(256, 1)
gemm_mma_split(const __nv_bfloat16* __restrict__ Ahi,
               const __nv_bfloat16* __restrict__ Alo,
               const __nv_bfloat16* __restrict__ Whi,
               const __nv_bfloat16* __restrict__ Wlo,
               const float* __restrict__ bias,
               float* __restrict__ C, int N, int Kp)
{
    extern __shared__ __align__(16) char smem[];
    const int tid = threadIdx.x;
    const int lane = tid & 31;
    const int wid = tid >> 5;
    const int wm = wid & 1, wn = wid >> 1;
    const int m0c = blockIdx.y * 128, n0c = blockIdx.x * 128;
    const int nchunks = Kp >> 6;
    const uint32_t sbase = smem_u32(smem);
    const __nv_bfloat16* bases[4] = { Ahi, Alo, Whi, Wlo };

    auto load_chunk = [&](int c, int s) {
        const uint32_t st = sbase + s * GSTAGE;
        #pragma unroll
        for (int q = 0; q < 16; q++) {
            int g = tid + q * 256;
            int tile = g >> 10, p = g & 1023;
            int r = p >> 3, seg = p & 7;
            int rowbase = (tile < 2) ? m0c : n0c;
            CP16(st + tile * GTILE + r * GSTR + seg * 16,
                 bases[tile] + (size_t)(rowbase + r) * Kp + c * 64 + seg * 8);
        }
        CP_COMMIT();
    };

    float acc[16][4];
    #pragma unroll
    for (int i = 0; i < 16; i++)
        #pragma unroll
        for (int j = 0; j < 4; j++) acc[i][j] = 0.f;

    load_chunk(0, 0);
    load_chunk(1, 1);
    for (int c = 0; c < nchunks; c++) {
        if (c + 1 < nchunks) { CP_WAIT(1); } else { CP_WAIT(0); }
        __syncthreads();
        if (c + 2 < nchunks) load_chunk(c + 2, (c + 2) % 3);
        const uint32_t st = sbase + (c % 3) * GSTAGE;
        #pragma unroll
        for (int kk = 0; kk < 4; kk++) {
            uint32_t ahi[4][4], alo[4][4], bhi[4][2], blo[4][2];
            #pragma unroll
            for (int i = 0; i < 4; i++) {
                int row = wm * 64 + i * 16 + (lane & 15);
                uint32_t off = row * GSTR + kk * 32 + (lane >> 4) * 16;
                ldsm4(ahi[i], st + off);
                ldsm4(alo[i], st + GTILE + off);
            }
            #pragma unroll
            for (int j = 0; j < 4; j++) {
                int row = wn * 32 + j * 8 + (lane & 7);
                uint32_t off = row * GSTR + kk * 32 + ((lane >> 3) & 1) * 16;
                ldsm2(bhi[j], st + 2 * GTILE + off);
                ldsm2(blo[j], st + 3 * GTILE + off);
            }
            #pragma unroll
            for (int i = 0; i < 4; i++)
                #pragma unroll
                for (int j = 0; j < 4; j++) {
                    mma16816(acc[i * 4 + j], ahi[i], bhi[j]);
                    mma16816(acc[i * 4 + j], ahi[i], blo[j]);
                    mma16816(acc[i * 4 + j], alo[i], bhi[j]);
                }
        }
    }
    __syncthreads();
    #pragma unroll
    for (int i = 0; i < 4; i++) {
        int m = m0c + wm * 64 + i * 16 + (lane >> 2);
        #pragma unroll
        for (int j = 0; j < 4; j++) {
            int n = n0c + wn * 32 + j * 8 + (lane & 3) * 2;
            float b0 = bias[n], b1 = bias[n + 1];
            float* a = acc[i * 4 + j];
            float2 v0 = { a[0] + b0, a[1] + b1 };
            float2 v1 = { a[2] + b0, a[3] + b1 };
            *reinterpret_cast<float2*>(C + (size_t)m * N + n) = v0;
            *reinterpret_cast<float2*>(C + (size_t)(m + 8) * N + n) = v1;
        }
    }
}

// ---------------- PERSISTENT scan: resident W-hi + cp.async pipeline --------
// YHIST=true (L0): h history lives in the y arrays (read t_prev, write t);
// no ping-pong writes. YHIST=false (L1): ping-pong hhi/hlo + hfin at s=63.
#define ASTR 144
#define WHI_B (96 * 1024)
template<int MROWS, bool YHIST>
__global__ void __launch_bounds__(256, 1)
gru_scan_wres(__nv_bfloat16* __restrict__ hhi_A, __nv_bfloat16* __restrict__ hlo_A,
              __nv_bfloat16* __restrict__ hhi_B, __nv_bfloat16* __restrict__ hlo_B,
              const float* __restrict__ gx, int gx_ld, int gx_ds,
              const __nv_bfloat16* __restrict__ whh_hi,
              const __nv_bfloat16* __restrict__ whh_lo,
              const float* __restrict__ bhh,
              __nv_bfloat16* __restrict__ y_hi, __nv_bfloat16* __restrict__ y_lo,
              float* __restrict__ hfin,
              unsigned* __restrict__ bars)
{
    constexpr int A_PL = MROWS * ASTR;
    constexpr int WLO_PL = 96 * ASTR;
    constexpr int STG = 2 * A_PL + WLO_PL;
    constexpr int NCH = 8;
    constexpr int A4 = MROWS * 8;
    constexpr int MFRG = MROWS / 32;
    constexpr int NE = MFRG * 4;

    extern __shared__ __align__(16) char smem[];
    const int tid = threadIdx.x;
    const int lane = tid & 31;
    const int wid = tid >> 5;
    const int wm = wid & 1, wn = wid >> 1;
    const int d  = blockIdx.z;
    const int b0 = blockIdx.x * MROWS;
    const int j0 = blockIdx.y * 32;
    const uint32_t sb = smem_u32(smem);
    const uint32_t sst = sb + WHI_B;
    unsigned* ctr = bars + (blockIdx.x * gridDim.z + blockIdx.z) * 32;
    const unsigned members = gridDim.y;

    const __nv_bfloat16* Wl = whh_lo + (size_t)d * G_ * H_;

    auto load_Wlo = [&](int c, int st) {
        const uint32_t base = sst + st * STG + 2 * A_PL;
        #pragma unroll
        for (int q = 0; q < 3; q++) {
            int g = tid + q * 256;
            int row = g >> 3, seg = g & 7;
            int grow = (row >> 5) * H_ + j0 + (row & 31);
            CP16(base + row * ASTR + seg * 16, Wl + (size_t)grow * H_ + c * 64 + seg * 8);
        }
    };

    {
        const __nv_bfloat16* Wh = whh_hi + (size_t)d * G_ * H_;
        for (int g = tid; g < 96 * 64; g += 256) {
            int row = g >> 6, seg = g & 63;
            int grow = (row >> 5) * H_ + j0 + (row & 31);
            uint32_t off = (row << 10) + (((uint32_t)seg * 16) ^ ((row & 7) << 4));
            CP16(sb + off, Wh + (size_t)grow * H_ + seg * 8);
        }
        CP_COMMIT(); CP_WAIT(0);
        __syncthreads();
    }
    const float* bhh_d = bhh + d * G_;

    int eb[NE], ej[NE];
    {
        int q = 0;
        #pragma unroll
        for (int i = 0; i < MFRG; i++)
            #pragma unroll
            for (int half = 0; half < 2; half++)
                #pragma unroll
                for (int e = 0; e < 2; e++) {
                    eb[q] = b0 + wm * (MROWS / 2) + i * 16 + (lane >> 2) + half * 8;
                    ej[q] = j0 + wn * 8 + (lane & 3) * 2 + e;
                    q++;
                }
    }

    float hprev[NE];
    #pragma unroll
    for (int q = 0; q < NE; q++) hprev[q] = 0.f;

    float gxp[NE][3];
    auto prefetch_gx = [&](int ss) {
        const int tt = (d == 0) ? ss : (T_ - 1 - ss);
        #pragma unroll
        for (int q = 0; q < NE; q++) {
            const float* gxr = gx + ((size_t)tt * B_ + eb[q]) * gx_ld + (size_t)d * gx_ds;
            gxp[q][0] = __ldcg(gxr + ej[q]);
            gxp[q][1] = __ldcg(gxr + H_ + ej[q]);
            gxp[q][2] = __ldcg(gxr + 2 * H_ + ej[q]);
        }
    };
    prefetch_gx(0);

    const __nv_bfloat16 *phh = hhi_A, *phl = hlo_A;
    __nv_bfloat16 *nhh = hhi_B, *nhl = hlo_B;

    for (int s = 0; s < T_; s++) {
        const int t = (d == 0) ? s : (T_ - 1 - s);
        const int tp = (d == 0) ? t - 1 : t + 1;   // time index of h(s-1)

        float acc[3][MFRG][4];
        #pragma unroll
        for (int g = 0; g < 3; g++)
            #pragma unroll
            for (int i = 0; i < MFRG; i++)
                #pragma unroll
                for (int r = 0; r < 4; r++) acc[g][i][r] = 0.f;

        if (s > 0) {
            const __nv_bfloat16* Ah;
            const __nv_bfloat16* Al;
            size_t arow_stride;
            if (YHIST) {
                Ah = y_hi + ((size_t)tp * B_) * (2 * H_) + (size_t)d * H_;
                Al = y_lo + ((size_t)tp * B_) * (2 * H_) + (size_t)d * H_;
                arow_stride = 2 * H_;
            } else {
                Ah = phh + (size_t)d * B_ * H_;
                Al = phl + (size_t)d * B_ * H_;
                arow_stride = H_;
            }

            auto load_A = [&](int c, int st) {
                const uint32_t base = sst + st * STG;
                #pragma unroll
                for (int q = 0; q < (2 * A4) / 256; q++) {
                    int g = tid + q * 256;
                    int plane = (g >= A4);
                    int p = plane ? g - A4 : g;
                    int row = p >> 3, seg = p & 7;
                    CP16(base + plane * A_PL + row * ASTR + seg * 16,
                         (plane ? Al : Ah) + (size_t)(b0 + row) * arow_stride + c * 64 + seg * 8);
                }
            };

            load_A(0, 0); CP_COMMIT();
            for (int c = 0; c < NCH; c++) {
                const int st = c & 1;
                if (c + 1 < NCH) {
                    load_A(c + 1, st ^ 1);
                    if (c + 1 >= 2) load_Wlo(c + 1, st ^ 1);
                    CP_COMMIT();
                    CP_WAIT(1);
                } else {
                    CP_WAIT(0);
                }
                __syncthreads();
                const uint32_t base = sst + st * STG;
                #pragma unroll
                for (int kk = 0; kk < 4; kk++) {
                    uint32_t ah[MFRG][4], al[MFRG][4];
                    #pragma unroll
                    for (int i = 0; i < MFRG; i++) {
                        int row = wm * (MROWS / 2) + i * 16 + (lane & 15);
                        uint32_t off = row * ASTR + kk * 32 + (lane >> 4) * 16;
                        ldsm4(ah[i], base + off);
                        ldsm4(al[i], base + A_PL + off);
                    }
                    uint32_t bh[3][2], bl[3][2];
                    #pragma unroll
                    for (int g = 0; g < 3; g++) {
                        int row = g * 32 + wn * 8 + (lane & 7);
                        uint32_t koff = (uint32_t)(c * 128 + kk * 32 + ((lane >> 3) & 1) * 16);
                        ldsm2(bh[g], sb + (row << 10) + (koff ^ ((row & 7) << 4)));
                        ldsm2(bl[g], base + 2 * A_PL + row * ASTR + kk * 32 + ((lane >> 3) & 1) * 16);
                    }
                    #pragma unroll
                    for (int g = 0; g < 3; g++)
                        #pragma unroll
                        for (int i = 0; i < MFRG; i++) {
                            mma16816(acc[g][i], ah[i], bh[g]);
                            mma16816(acc[g][i], ah[i], bl[g]);
                            mma16816(acc[g][i], al[i], bh[g]);
                        }
                }
                __syncthreads();
            }
        }

        // -------- register-local gate epilogue --------
        #pragma unroll
        for (int q = 0; q < NE; q++) {
            const int i = q >> 2;
            const int r2 = q & 3;
            const int j = ej[q];
            float ghr = acc[0][i][r2] + bhh_d[j];
            float ghz = acc[1][i][r2] + bhh_d[H_ + j];
            float ghn = acc[2][i][r2] + bhh_d[2 * H_ + j];
            float rg = sigm(gxp[q][0] + ghr);
            float zg = sigm(gxp[q][1] + ghz);
            float ng = tanh_(gxp[q][2] + rg * ghn);
            float hv = (1.f - zg) * ng + zg * hprev[q];
            hprev[q] = hv;
            __nv_bfloat16 hib = __float2bfloat16(hv);
            __nv_bfloat16 lob = __float2bfloat16(hv - __bfloat162float(hib));
            if (YHIST) {
                size_t yo = ((size_t)t * B_ + eb[q]) * (size_t)(2 * H_) + (size_t)d * H_ + j;
                y_hi[yo] = hib;
                y_lo[yo] = lob;
            } else {
                size_t ho = ((size_t)d * B_ + eb[q]) * H_ + j;
                nhh[ho] = hib;
                nhl[ho] = lob;
                if (hfin && s == T_ - 1)
                    hfin[(size_t)eb[q] * H_ + j] = hv;
            }
        }

        if (s + 1 < T_) {
            __syncthreads();
            if (tid == 0) { __threadfence(); atomicAdd(ctr, 1u); }   // arrive EARLY
            load_Wlo(0, 0);
            load_Wlo(1, 1);
            CP_COMMIT();
            prefetch_gx(s + 1);
            if (tid == 0) {
                volatile unsigned* vc = ctr;
                while (*vc < (unsigned)(s + 1) * members) { }
                __threadfence();
            }
            __syncthreads();
        }

        if (!YHIST) {
            const __nv_bfloat16* th = phh; phh = nhh; nhh = (__nv_bfloat16*)th;
            const __nv_bfloat16* tl = phl; phl = nhl; nhl = (__nv_bfloat16*)tl;
        }
    }
}

// ---------------- tail kernels ----------------------------------------------
__global__ void bwd1_gates(const float* __restrict__ gxb,
                           const float* __restrict__ bhh,
                           float* __restrict__ out)
{
    int idx = blockIdx.x * blockDim.x + threadIdx.x;
    if (idx >= B_ * H_) return;
    int b = idx >> 9, j = idx & 511;
    const float* r0 = gxb + (size_t)b * G_;
    float rg = sigm(r0[j] + bhh[j]);
    float zg = sigm(r0[H_ + j] + bhh[H_ + j]);
    float ng = tanh_(r0[2 * H_ + j] + rg * bhh[2 * H_ + j]);
    out[idx] = (1.f - zg) * ng;
}

__global__ void fc_kernel(const float* __restrict__ hf, const float* __restrict__ hb,
                          const float* __restrict__ fcw, const float* __restrict__ fcb,
                          float* __restrict__ out)
{
    int b = blockIdx.x, tid = threadIdx.x;
    float s0 = 0.f, s1 = 0.f;
    for (int j = tid; j < 1024; j += 256) {
        float v = (j < 512) ? hf[(size_t)b * 512 + j] : hb[(size_t)b * 512 + (j - 512)];
        s0 += v * fcw[j];
        s1 += v * fcw[1024 + j];
    }
    __shared__ float red0[256], red1[256];
    red0[tid] = s0; red1[tid] = s1;
    __syncthreads();
    for (int off = 128; off > 0; off >>= 1) {
        if (tid < off) { red0[tid] += red0[tid + off]; red1[tid] += red1[tid + off]; }
        __syncthreads();
    }
    if (tid == 0) {
        out[b * 2 + 0] = red0[0] + fcb[0];
        out[b * 2 + 1] = red1[0] + fcb[1];
    }
}

// ---------------- launch -----------------------------------------------------
extern "C" void kernel_launch(void* const* d_in, const int* in_sizes, int n_in,
                              void* d_out, int out_size)
{
    (void)in_sizes; (void)n_in; (void)out_size;
    const int*   tokens = (const int*)  d_in[0];
    const float* emb    = (const float*)d_in[1];
    const float* w_ih0  = (const float*)d_in[2];
    const float* w_hh0  = (const float*)d_in[3];
    const float* b_ih0  = (const float*)d_in[4];
    const float* b_hh0  = (const float*)d_in[5];
    const float* w_ih1  = (const float*)d_in[6];
    const float* w_hh1  = (const float*)d_in[7];
    const float* b_ih1  = (const float*)d_in[8];
    const float* b_hh1  = (const float*)d_in[9];
    const float* fc_w   = (const float*)d_in[10];
    const float* fc_b   = (const float*)d_in[11];
    float* out = (float*)d_out;

    float *pgx0, *pgx1, *pgx1b, *phfin, *plastb;
    unsigned* pbar;
    cudaGetSymbolAddress((void**)&pgx0,   g_gx0);
    cudaGetSymbolAddress((void**)&pgx1,   g_gx1);
    cudaGetSymbolAddress((void**)&pgx1b,  g_gx1b);
    cudaGetSymbolAddress((void**)&phfin,  g_hfin);
    cudaGetSymbolAddress((void**)&plastb, g_lastb);
    cudaGetSymbolAddress((void**)&pbar,   g_bar);
    __nv_bfloat16 *phhi, *phlo, *pa0hi, *pa0lo, *pw0hi, *pw0lo;
    __nv_bfloat16 *pa1hi, *pa1lo, *pw1hi, *pw1lo, *pwh0hi, *pwh0lo, *pwh1hi, *pwh1lo;
    cudaGetSymbolAddress((void**)&phhi,  g_hhi);
    cudaGetSymbolAddress((void**)&phlo,  g_hlo);
    cudaGetSymbolAddress((void**)&pa0hi, g_a0hi);
    cudaGetSymbolAddress((void**)&pa0lo, g_a0lo);
    cudaGetSymbolAddress((void**)&pw0hi, g_w0hi);
    cudaGetSymbolAddress((void**)&pw0lo, g_w0lo);
    cudaGetSymbolAddress((void**)&pa1hi, g_a1hi);
    cudaGetSymbolAddress((void**)&pa1lo, g_a1lo);
    cudaGetSymbolAddress((void**)&pw1hi, g_w1hi);
    cudaGetSymbolAddress((void**)&pw1lo, g_w1lo);
    cudaGetSymbolAddress((void**)&pwh0hi, g_wh0hi);
    cudaGetSymbolAddress((void**)&pwh0lo, g_wh0lo);
    cudaGetSymbolAddress((void**)&pwh1hi, g_wh1hi);
    cudaGetSymbolAddress((void**)&pwh1lo, g_wh1lo);

    const int GSM  = 3 * GSTAGE;                                  // 221184
    const int SCM0 = WHI_B + 2 * (2 * 128 * ASTR + 96 * ASTR);    // 199680
    const int SCM1 = WHI_B + 2 * (2 * 64 * ASTR + 96 * ASTR);     // 162816
    cudaFuncSetAttribute(gemm_mma_split, cudaFuncAttributeMaxDynamicSharedMemorySize, GSM);
    cudaFuncSetAttribute((const void*)gru_scan_wres<128, true>,
                         cudaFuncAttributeMaxDynamicSharedMemorySize, SCM0);
    cudaFuncSetAttribute((const void*)gru_scan_wres<64, false>,
                         cudaFuncAttributeMaxDynamicSharedMemorySize, SCM1);

    const size_t HB = (size_t)2 * B_ * H_;
    const int MT = B_ * T_;

    // 1) prep
    split_pad_kernel<<<(2 * G_ * KP0 + 255) / 256, 256>>>(w_ih0, pw0hi, pw0lo, 2 * G_, 300, KP0);
    embed_split_kernel<<<MT, 128>>>(tokens, emb, pa0hi, pa0lo);
    zero_ctr_kernel<<<8, 256>>>(pbar, 2048);
    split_pad_kernel<<<(2 * G_ * H_ + 255) / 256, 256>>>(w_hh0, pwh0hi, pwh0lo, 2 * G_, H_, H_);
    // 2) layer0 input GEMM: gx0[32768][3072]
    gemm_mma_split<<<dim3(2 * G_ / 128, MT / 128), 256, GSM>>>(
        pa0hi, pa0lo, pw0hi, pw0lo, b_ih0, pgx0, 2 * G_, KP0);
    // 3) layer0 bidirectional scan (h history lives in the y arrays)
    gru_scan_wres<128, true><<<dim3(4, 16, 2), 256, SCM0>>>(
        phhi, phlo, phhi + HB, phlo + HB,
        pgx0, 2 * G_, G_, pwh0hi, pwh0lo, b_hh0, pa1hi, pa1lo,
        (float*)nullptr, pbar);
    // 4) remaining splits
    split_pad_kernel<<<(int)(((size_t)2 * G_ * 1024 + 255) / 256), 256>>>(w_ih1, pw1hi, pw1lo, 2 * G_, 1024, 1024);
    split_pad_kernel<<<(2 * G_ * H_ + 255) / 256, 256>>>(w_hh1, pwh1hi, pwh1lo, 2 * G_, H_, H_);
    // 5) layer1 fwd input GEMM: gx1[32768][1536]
    gemm_mma_split<<<dim3(G_ / 128, MT / 128), 256, GSM>>>(
        pa1hi, pa1lo, pw1hi, pw1lo, b_ih1, pgx1, G_, 1024);
    // 6) layer1 forward scan (ping-pong h buffers)
    gru_scan_wres<64, false><<<dim3(8, 16, 1), 256, SCM1>>>(
        phhi, phlo, phhi + HB, phlo + HB,
        pgx1, G_, 0, pwh1hi, pwh1lo, b_hh1,
        (__nv_bfloat16*)nullptr, (__nv_bfloat16*)nullptr, phfin, pbar + 1024);
    // 7) layer1 backward = ONE step at t=T-1 (h0=0)
    gemm_mma_split<<<dim3(G_ / 128, B_ / 128), 256, GSM>>>(
        pa1hi + (size_t)(T_ - 1) * B_ * 1024, pa1lo + (size_t)(T_ - 1) * B_ * 1024,
        pw1hi + (size_t)G_ * 1024, pw1lo + (size_t)G_ * 1024,
        b_ih1 + G_, pgx1b, G_, 1024);
    bwd1_gates<<<(B_ * H_ + 255) / 256, 256>>>(pgx1b, b_hh1 + G_, plastb);
    // 8) FC head
    fc_kernel<<<B_, 256>>>(phfin, plastb, fc_w, fc_b, out);
}